// round 16
// baseline (speedup 1.0000x reference)
#include <cuda_runtime.h>

// out[i] = sum_b sum_j x1[b,j] * x2[b,(i-j) mod 1024]
// R16: R15 four-step shuffle FFT body (unchanged) + shorter epilogue:
// warp-shuffle row reduction (one fewer CTA barrier, no serial 32-iter sum).

#define BSZ 128
#define D   1024
#define PAD 33

__device__ float    g_partial[BSZ * D];
__device__ unsigned g_counter = 0;

__device__ __forceinline__ float2 cmul(float2 a, float2 w) {
    return make_float2(a.x * w.x - a.y * w.y, a.x * w.y + a.y * w.x);
}
__device__ __forceinline__ float2 cmulc(float2 a, float2 w) {   // a * conj(w)
    return make_float2(a.x * w.x + a.y * w.y, a.y * w.x - a.x * w.y);
}
__device__ __forceinline__ float2 cadd(float2 a, float2 b) { return make_float2(a.x + b.x, a.y + b.y); }
__device__ __forceinline__ float2 csub(float2 a, float2 b) { return make_float2(a.x - b.x, a.y - b.y); }

__device__ __forceinline__ float2 shflx(float2 v, int h) {
    return make_float2(__shfl_xor_sync(0xFFFFFFFFu, v.x, h),
                       __shfl_xor_sync(0xFFFFFFFFu, v.y, h));
}

// 5-stage 32-pt DIF FFT across lanes, single instance.
// Input natural order (lane = index); output: lane l holds result[rev5(l)].
template <bool INV>
__device__ __forceinline__ float2 fft32(float2 V, const float2 tw[5], int lane) {
    #pragma unroll
    for (int s = 0; s < 5; s++) {
        const int  h  = 16 >> s;
        const bool up = (lane & h) != 0;
        const float2 p   = shflx(V, h);
        const float2 sum = cadd(p, V);
        const float2 dif = csub(p, V);
        const float2 m   = INV ? cmulc(dif, tw[s]) : cmul(dif, tw[s]);
        V = up ? m : sum;
    }
    return V;
}

// Spectrum unpack + pointwise product: P[k] from Z[k], Z[(D-k)%D].
__device__ __forceinline__ float2 spec_prod(float2 zk, float2 zm) {
    const float a = zk.x, bb = zk.y, c = zm.x, d = zm.y;
    const float x1r = a + c,  x1i = bb - d;
    const float x2r = bb + d, x2i = c - a;
    return make_float2(0.25f * (x1r * x2r - x1i * x2i),
                       0.25f * (x1r * x2i + x1i * x2r));
}

__global__ void __launch_bounds__(1024, 1)
fftconv10_kernel(const float* __restrict__ x1, const float* __restrict__ x2,
                 float* __restrict__ out) {
    __shared__ float2 sA[PAD * 32];
    __shared__ float2 sB[PAD * 32];
    __shared__ float  sR[PAD * 32];
    __shared__ float2 roots[D];     // roots[m] = e^{+2*pi*i*m/1024}
    __shared__ float2 tw32[32];     // tw32[m]  = e^{-2*pi*i*m/32}
    __shared__ float  red[32];

    const int tid  = threadIdx.x;
    const int lane = tid & 31;
    const int w    = tid >> 5;      // warp 0..31 = FFT instance id
    const int b    = blockIdx.x;

    // ---- issue global loads FIRST (coalesced) ----
    const float a0 = x1[b * D + tid];
    const float c0 = x2[b * D + tid];

    // ---- twiddle tables: 2 MUFU per thread total ----
    {
        const int m  = tid;                       // 0..1023
        const int mm = (m >= 512) ? m - 512 : m;  // sign folded below
        float sn, cs;
        __sincosf(0.006135923151542565f * (float)mm, &sn, &cs);  // 2*pi/1024
        roots[m] = (m >= 512) ? make_float2(-cs, -sn) : make_float2(cs, sn);
    }
    if (tid < 32) {
        float sn, cs;
        __sincosf(-0.19634954084936207f * (float)tid, &sn, &cs); // -2*pi/32
        tw32[tid] = make_float2(cs, sn);
    }
    const int rv = (int)(__brev((unsigned)lane) >> 27);  // rev5(lane)

    // ---- pack z = x1 + i*x2 into sA[n] at 33*(n>>5) + (n&31) ----
    sA[PAD * w + lane] = make_float2(a0, c0);
    __syncthreads();   // covers tables + pack

    // ---- stage twiddles from table: tw[s] = tw32[(lane&(h-1))<<s] ----
    float2 tw[5];
    #pragma unroll
    for (int s = 0; s < 5; s++)
        tw[s] = tw32[(lane & ((16 >> s) - 1)) << s];

    // four-step twiddle: fwd = conj(myroot), inv = myroot (same index w*rv)
    const float2 myroot = roots[(w * rv) & (D - 1)];

    float2 V;

    // ---- fwd inner: FFT over a-index (lane), instance col = w ----
    V = sA[PAD * lane + w];
    V = fft32<false>(V, tw, lane);
    V = cmulc(V, myroot);                 // e^{-2pi*i*w*rv/1024}
    sB[PAD * rv + w] = V;                 // transpose-store
    __syncthreads();

    // ---- fwd outer: FFT over b-index (lane), instance c = w ----
    V = sB[PAD * w + lane];
    V = fft32<false>(V, tw, lane);
    sA[PAD * w + rv] = V;                 // spectrum at sA[33*c + d]
    __syncthreads();

    // ---- product + inv inner: instance c = w, lane = d ----
    {
        const float2 zk = sA[PAD * w + lane];
        const int c2 = (32 - w) & 31;
        const int d2 = (w == 0) ? ((32 - lane) & 31) : (31 - lane);
        const float2 zm = sA[PAD * c2 + d2];
        V = spec_prod(zk, zm);
    }
    V = fft32<true>(V, tw, lane);
    V = cmul(V, myroot);                  // e^{+2pi*i*rv*w/1024}
    sB[PAD * rv + w] = V;
    __syncthreads();

    // ---- inv outer: instance bcol = w, lane = c ----
    V = sB[PAD * w + lane];
    V = fft32<true>(V, tw, lane);
    sR[PAD * rv + w] = V.x * (1.0f / D);  // y[32*rv + w], real by construction
    __syncthreads();

    // ---- coalesced writeout of y_b (one float per thread) ----
    g_partial[b * D + tid] = sR[PAD * (tid >> 5) + (tid & 31)];

    // ---- single cross-CTA barrier (monotonic ticket, replay-safe) ----
    __syncthreads();
    if (tid == 0) {
        __threadfence();  // release g_partial writes
        const unsigned old    = atomicAdd(&g_counter, 1u);
        const unsigned target = old - (old & (BSZ - 1)) + BSZ;
        unsigned cur;
        do {
            asm volatile("ld.global.acquire.gpu.u32 %0, [%1];"
                         : "=r"(cur) : "l"(&g_counter));
        } while ((int)(cur - target) < 0);
    }
    __syncthreads();

    // ---- epilogue: CTA c owns outputs [8c, 8c+8); warp-shuffle reduction ----
    // warp w: output o = w&7, row quarter q = w>>3; thread handles row q*32+lane.
    {
        const int o = w & 7;
        const int q = w >> 3;
        const int i = blockIdx.x * 8 + o;
        float s = __ldcg(&g_partial[(q * 32 + lane) * D + i]);
        #pragma unroll
        for (int m = 16; m > 0; m >>= 1)
            s += __shfl_xor_sync(0xFFFFFFFFu, s, m);
        if (lane == 0) red[w] = s;        // red[q*8 + o]
        __syncthreads();
        if (tid < 8) {
            out[blockIdx.x * 8 + tid] =
                red[tid] + red[tid + 8] + red[tid + 16] + red[tid + 24];
        }
    }
}

extern "C" void kernel_launch(void* const* d_in, const int* in_sizes, int n_in,
                              void* d_out, int out_size) {
    const float* x1  = (const float*)d_in[0];  // (128, 1024) fp32
    const float* x2  = (const float*)d_in[1];  // (128, 1024) fp32
    float*       out = (float*)d_out;          // (1,1,1024) fp32

    fftconv10_kernel<<<BSZ, 1024>>>(x1, x2, out);
}

// round 17
// speedup vs baseline: 1.2610x; 1.2610x over previous
#include <cuda_runtime.h>

// out[i] = sum_b sum_j x1[b,j] * x2[b,(i-j) mod 1024]
// FINAL (= R15, the measured-best kernel): four-step shuffle FFT (1024=32x32),
// 1024 threads/CTA, one FFT instance per thread, smem twiddle tables,
// one global ticket barrier, coalesced distributed reduction.

#define BSZ 128
#define D   1024
#define PAD 33

__device__ float    g_partial[BSZ * D];
__device__ unsigned g_counter = 0;

__device__ __forceinline__ float2 cmul(float2 a, float2 w) {
    return make_float2(a.x * w.x - a.y * w.y, a.x * w.y + a.y * w.x);
}
__device__ __forceinline__ float2 cmulc(float2 a, float2 w) {   // a * conj(w)
    return make_float2(a.x * w.x + a.y * w.y, a.y * w.x - a.x * w.y);
}
__device__ __forceinline__ float2 cadd(float2 a, float2 b) { return make_float2(a.x + b.x, a.y + b.y); }
__device__ __forceinline__ float2 csub(float2 a, float2 b) { return make_float2(a.x - b.x, a.y - b.y); }

__device__ __forceinline__ float2 shflx(float2 v, int h) {
    return make_float2(__shfl_xor_sync(0xFFFFFFFFu, v.x, h),
                       __shfl_xor_sync(0xFFFFFFFFu, v.y, h));
}

// 5-stage 32-pt DIF FFT across lanes, single instance.
// Input natural order (lane = index); output: lane l holds result[rev5(l)].
template <bool INV>
__device__ __forceinline__ float2 fft32(float2 V, const float2 tw[5], int lane) {
    #pragma unroll
    for (int s = 0; s < 5; s++) {
        const int  h  = 16 >> s;
        const bool up = (lane & h) != 0;
        const float2 p   = shflx(V, h);
        const float2 sum = cadd(p, V);
        const float2 dif = csub(p, V);
        const float2 m   = INV ? cmulc(dif, tw[s]) : cmul(dif, tw[s]);
        V = up ? m : sum;
    }
    return V;
}

// Spectrum unpack + pointwise product: P[k] from Z[k], Z[(D-k)%D].
__device__ __forceinline__ float2 spec_prod(float2 zk, float2 zm) {
    const float a = zk.x, bb = zk.y, c = zm.x, d = zm.y;
    const float x1r = a + c,  x1i = bb - d;
    const float x2r = bb + d, x2i = c - a;
    return make_float2(0.25f * (x1r * x2r - x1i * x2i),
                       0.25f * (x1r * x2i + x1i * x2r));
}

__global__ void __launch_bounds__(1024, 1)
fftconv_final_kernel(const float* __restrict__ x1, const float* __restrict__ x2,
                     float* __restrict__ out) {
    __shared__ float2 sA[PAD * 32];
    __shared__ float2 sB[PAD * 32];
    __shared__ float  sR[PAD * 32];
    __shared__ float2 roots[D];     // roots[m] = e^{+2*pi*i*m/1024}
    __shared__ float2 tw32[32];     // tw32[m]  = e^{-2*pi*i*m/32}
    __shared__ float  red[1024];

    const int tid  = threadIdx.x;
    const int lane = tid & 31;
    const int w    = tid >> 5;      // warp 0..31 = FFT instance id
    const int b    = blockIdx.x;

    // ---- issue global loads FIRST (coalesced) ----
    const float a0 = x1[b * D + tid];
    const float c0 = x2[b * D + tid];

    // ---- twiddle tables: 2 MUFU per thread total ----
    {
        const int m  = tid;                       // 0..1023
        const int mm = (m >= 512) ? m - 512 : m;  // sign folded below
        float sn, cs;
        __sincosf(0.006135923151542565f * (float)mm, &sn, &cs);  // 2*pi/1024
        roots[m] = (m >= 512) ? make_float2(-cs, -sn) : make_float2(cs, sn);
    }
    if (tid < 32) {
        float sn, cs;
        __sincosf(-0.19634954084936207f * (float)tid, &sn, &cs); // -2*pi/32
        tw32[tid] = make_float2(cs, sn);
    }
    const int rv = (int)(__brev((unsigned)lane) >> 27);  // rev5(lane)

    // ---- pack z = x1 + i*x2 into sA[n] at 33*(n>>5) + (n&31) ----
    sA[PAD * w + lane] = make_float2(a0, c0);
    __syncthreads();   // covers tables + pack

    // ---- stage twiddles from table: tw[s] = tw32[(lane&(h-1))<<s] ----
    float2 tw[5];
    #pragma unroll
    for (int s = 0; s < 5; s++)
        tw[s] = tw32[(lane & ((16 >> s) - 1)) << s];

    // four-step twiddle: fwd = conj(myroot), inv = myroot (same index w*rv)
    const float2 myroot = roots[(w * rv) & (D - 1)];

    float2 V;

    // ---- fwd inner: FFT over a-index (lane), instance col = w ----
    V = sA[PAD * lane + w];
    V = fft32<false>(V, tw, lane);
    V = cmulc(V, myroot);                 // e^{-2pi*i*w*rv/1024}
    sB[PAD * rv + w] = V;                 // transpose-store
    __syncthreads();

    // ---- fwd outer: FFT over b-index (lane), instance c = w ----
    V = sB[PAD * w + lane];
    V = fft32<false>(V, tw, lane);
    sA[PAD * w + rv] = V;                 // spectrum at sA[33*c + d]
    __syncthreads();

    // ---- product + inv inner: instance c = w, lane = d ----
    {
        const float2 zk = sA[PAD * w + lane];
        const int c2 = (32 - w) & 31;
        const int d2 = (w == 0) ? ((32 - lane) & 31) : (31 - lane);
        const float2 zm = sA[PAD * c2 + d2];
        V = spec_prod(zk, zm);
    }
    V = fft32<true>(V, tw, lane);
    V = cmul(V, myroot);                  // e^{+2pi*i*rv*w/1024}
    sB[PAD * rv + w] = V;
    __syncthreads();

    // ---- inv outer: instance bcol = w, lane = c ----
    V = sB[PAD * w + lane];
    V = fft32<true>(V, tw, lane);
    sR[PAD * rv + w] = V.x * (1.0f / D);  // y[32*rv + w], real by construction
    __syncthreads();

    // ---- coalesced writeout of y_b (one float per thread) ----
    g_partial[b * D + tid] = sR[PAD * (tid >> 5) + (tid & 31)];

    // ---- single cross-CTA barrier (monotonic ticket, replay-safe) ----
    __syncthreads();
    if (tid == 0) {
        __threadfence();  // release g_partial writes
        const unsigned old    = atomicAdd(&g_counter, 1u);
        const unsigned target = old - (old & (BSZ - 1)) + BSZ;
        unsigned cur;
        do {
            asm volatile("ld.global.acquire.gpu.u32 %0, [%1];"
                         : "=r"(cur) : "l"(&g_counter));
        } while ((int)(cur - target) < 0);
    }
    __syncthreads();

    // ---- fused deterministic reduction: CTA c owns outputs [8c, 8c+8) ----
    // brow = tid>>3, i = 8c + (tid&7): each warp touches 4 rows x 32B sectors
    // (coalesced — the R16 experiment proved layout dominates here).
    {
        const int i    = blockIdx.x * 8 + (tid & 7);
        const int brow = tid >> 3;  // 0..127 — one load per thread
        red[tid] = __ldcg(&g_partial[brow * D + i]);
        __syncthreads();
        if (tid < 256) {
            red[tid] = red[tid] + red[tid + 256] + red[tid + 512] + red[tid + 768];
        }
        __syncthreads();
        if (tid < 8) {
            float t = 0.f;
            #pragma unroll
            for (int m = 0; m < 32; m++) t += red[tid + 8 * m];
            out[blockIdx.x * 8 + tid] = t;
        }
    }
}

extern "C" void kernel_launch(void* const* d_in, const int* in_sizes, int n_in,
                              void* d_out, int out_size) {
    const float* x1  = (const float*)d_in[0];  // (128, 1024) fp32
    const float* x2  = (const float*)d_in[1];  // (128, 1024) fp32
    float*       out = (float*)d_out;          // (1,1,1024) fp32

    fftconv_final_kernel<<<BSZ, 1024>>>(x1, x2, out);
}